// round 14
// baseline (speedup 1.0000x reference)
#include <cuda_runtime.h>
#include <cuda_bf16.h>
#include <cstdint>

#define D 128
#define ALPHA 0.5f
#define MAX_NODES 50000
#define MAX_EDGES 800000
#define NB 296            // persistent grid: 2 CTAs/SM on 148 SMs, all co-resident
#define NT 256
#define GB 96             // graph blocks (block < GB); rest do GEMM

// ---------------- scratch (static device globals; no allocation) ----------------
__device__ float g_y_src[(size_t)MAX_NODES * D];   // alpha * (x @ W_src)
__device__ float g_y_dst[(size_t)MAX_NODES * D];   // (1-alpha) * (x @ W_dst)
__device__ int   g_outdeg[MAX_NODES];
__device__ int   g_indeg[MAX_NODES];
__device__ float g_dout[MAX_NODES];
__device__ float g_din[MAX_NODES];
__device__ int   g_ei[2 * MAX_EDGES];
__device__ int   g_rs[MAX_NODES];      // forward bucket start (by row)
__device__ int   g_cs[MAX_NODES];      // backward bucket start (by col)
__device__ int   g_rcur[MAX_NODES];
__device__ int   g_ccur[MAX_NODES];
__device__ int   g_fwd[MAX_EDGES];     // col indices, bucketed by row
__device__ int   g_bwd[MAX_EDGES];     // row indices, bucketed by col
__device__ unsigned g_base_f = 0, g_base_b = 0;

// global barrier (all NB blocks) + sub-barrier (GB graph blocks); generation-based
__device__ unsigned g_cnt = 0;
__device__ volatile unsigned g_gen = 0;
__device__ unsigned g_cnt2 = 0;
__device__ volatile unsigned g_gen2 = 0;

__device__ __forceinline__ void barrier_impl(unsigned* cnt, volatile unsigned* gen,
                                             int nblocks) {
    __syncthreads();
    if (threadIdx.x == 0) {
        unsigned my = *gen;
        __threadfence();
        if (atomicAdd(cnt, 1u) == (unsigned)(nblocks - 1)) {
            *cnt = 0;
            __threadfence();
            *gen = my + 1;
        } else {
            while (*gen == my) { }
        }
        __threadfence();
    }
    __syncthreads();
}
__device__ __forceinline__ void grid_barrier(int nb) { barrier_impl(&g_cnt, &g_gen, nb); }
__device__ __forceinline__ void sub_barrier()        { barrier_impl(&g_cnt2, &g_gen2, GB); }

// Dtype-agnostic index decode (exact for int32 and float32 encodings).
__device__ __forceinline__ int decode_idx(int v, int n) {
    if ((unsigned)v < (unsigned)n) return v;
    float f = __int_as_float(v);
    int r = (f > 0.0f) ? (int)f : 0;
    return ((unsigned)r < (unsigned)n) ? r : 0;
}

__device__ __forceinline__ uint32_t f2tf32(float f) {
    uint32_t u;
    asm("cvt.rna.tf32.f32 %0, %1;" : "=r"(u) : "f"(f));
    return u;
}

__device__ __forceinline__ void mma_tf32(float4& d,
                                         uint32_t a0, uint32_t a1, uint32_t a2, uint32_t a3,
                                         uint32_t b0, uint32_t b1) {
    asm volatile(
        "mma.sync.aligned.m16n8k8.row.col.f32.tf32.tf32.f32 "
        "{%0,%1,%2,%3}, {%4,%5,%6,%7}, {%8,%9}, {%0,%1,%2,%3};"
        : "+f"(d.x), "+f"(d.y), "+f"(d.z), "+f"(d.w)
        : "r"(a0), "r"(a1), "r"(a2), "r"(a3), "r"(b0), "r"(b1));
}

// GEMM tile: 64 rows x 128 cols, k-chunk 32, tf32 mma m16n8k8.
// Conflict-free strides: WSP%32==8 -> bank = 8*tig+gid; XSP%32==4 -> 4*gid+tig.
#define GEMM_TR 64
#define GEMM_KT 32
#define XSP 36
#define WSP 136

__global__ void __launch_bounds__(NT, 2)
fused_kernel(const float* __restrict__ x,
             const int* __restrict__ ei_raw,
             const float* __restrict__ W_src, const float* __restrict__ b_src,
             const float* __restrict__ W_dst, const float* __restrict__ b_dst,
             float* __restrict__ out,
             int N, int E) {
    __shared__ uint32_t Ws[GEMM_KT * WSP];   // 17.4 KB (tf32 bits)
    __shared__ uint32_t Xs[GEMM_TR * XSP];   // 9.2 KB  (tf32 bits)

    const int tid = threadIdx.x;
    const int nb = gridDim.x;
    const int bid = blockIdx.x;

    if (bid < GB) {
        // ================= GRAPH BLOCKS: decode -> degrees -> CSR =================
        const int gtid = bid * NT + tid;
        const int gstride = GB * NT;

        for (int i = gtid; i < N; i += gstride) {
            g_outdeg[i] = 0;
            g_indeg[i] = 0;
        }
        if (gtid == 0) { g_base_f = 0; g_base_b = 0; }
        sub_barrier();

        for (int i = gtid; i < 2 * E; i += gstride) {
            int v = decode_idx(ei_raw[i], N);
            g_ei[i] = v;
            if (i < E) atomicAdd(&g_outdeg[v], 1);
            else       atomicAdd(&g_indeg[v], 1);
        }
        sub_barrier();

        for (int i = gtid; i < N; i += gstride) {
            int od = g_outdeg[i];
            int id = g_indeg[i];
            g_dout[i] = (od > 0) ? rsqrtf((float)od) : 0.0f;
            g_din[i]  = (id > 0) ? rsqrtf((float)id) : 0.0f;
            int rs = (int)atomicAdd(&g_base_f, (unsigned)od);
            int cs = (int)atomicAdd(&g_base_b, (unsigned)id);
            g_rs[i] = rs;  g_rcur[i] = rs;
            g_cs[i] = cs;  g_ccur[i] = cs;
        }
        sub_barrier();

        for (int e = gtid; e < E; e += gstride) {
            int row = g_ei[e];
            int col = g_ei[E + e];
            g_fwd[atomicAdd(&g_rcur[row], 1)] = col;
            g_bwd[atomicAdd(&g_ccur[col], 1)] = row;
        }
    } else {
        // ================= GEMM BLOCKS: tf32 tensor-core GEMMs ====================
        const int tiles = (N + GEMM_TR - 1) / GEMM_TR;
        const int lane = tid & 31;
        const int warp = tid >> 5;
        const int gid = lane >> 2;       // 0..7
        const int tig = lane & 3;        // 0..3
        const int m0 = (warp & 3) * 16;  // warp's m offset in tile
        const int n0 = (warp >> 2) * 64; // warp's n offset

        for (int job = bid - GB; job < 2 * tiles; job += nb - GB) {
            const bool is_src = (job < tiles);
            const float* W = is_src ? W_src : W_dst;
            float* Y       = is_src ? g_y_src : g_y_dst;
            const float scale = is_src ? ALPHA : (1.0f - ALPHA);
            const int row0 = (is_src ? job : job - tiles) * GEMM_TR;

            float4 acc[8];
#pragma unroll
            for (int t = 0; t < 8; t++) acc[t] = make_float4(0.f, 0.f, 0.f, 0.f);

            for (int kt = 0; kt < D; kt += GEMM_KT) {
#pragma unroll
                for (int i = tid; i < GEMM_KT * (D / 4); i += NT) {
                    int kk = i >> 5, d4 = i & 31;
                    float4 v = ((const float4*)(W + (kt + kk) * D))[d4];
                    uint4 u = make_uint4(f2tf32(v.x), f2tf32(v.y),
                                         f2tf32(v.z), f2tf32(v.w));
                    *(uint4*)&Ws[kk * WSP + d4 * 4] = u;
                }
#pragma unroll
                for (int i = tid; i < GEMM_TR * (GEMM_KT / 4); i += NT) {
                    int r = i >> 3, c4 = i & 7;
                    int gr = row0 + r;
                    float4 v = (gr < N)
                        ? ((const float4*)(x + (size_t)gr * D + kt))[c4]
                        : make_float4(0.f, 0.f, 0.f, 0.f);
                    uint4 u = make_uint4(f2tf32(v.x), f2tf32(v.y),
                                         f2tf32(v.z), f2tf32(v.w));
                    *(uint4*)&Xs[r * XSP + c4 * 4] = u;
                }
                __syncthreads();

#pragma unroll
                for (int ks = 0; ks < GEMM_KT; ks += 8) {
                    uint32_t a0 = Xs[(m0 + gid)     * XSP + ks + tig];
                    uint32_t a1 = Xs[(m0 + gid + 8) * XSP + ks + tig];
                    uint32_t a2 = Xs[(m0 + gid)     * XSP + ks + tig + 4];
                    uint32_t a3 = Xs[(m0 + gid + 8) * XSP + ks + tig + 4];
#pragma unroll
                    for (int t = 0; t < 8; t++) {
                        uint32_t b0 = Ws[(ks + tig)     * WSP + n0 + t * 8 + gid];
                        uint32_t b1 = Ws[(ks + tig + 4) * WSP + n0 + t * 8 + gid];
                        mma_tf32(acc[t], a0, a1, a2, a3, b0, b1);
                    }
                }
                __syncthreads();
            }

            int r0 = row0 + m0 + gid;
            int r1 = r0 + 8;
#pragma unroll
            for (int t = 0; t < 8; t++) {
                int col = n0 + t * 8 + 2 * tig;
                if (r0 < N) {
                    float2 v = make_float2(scale * acc[t].x, scale * acc[t].y);
                    *(float2*)&Y[(size_t)r0 * D + col] = v;
                }
                if (r1 < N) {
                    float2 v = make_float2(scale * acc[t].z, scale * acc[t].w);
                    *(float2*)&Y[(size_t)r1 * D + col] = v;
                }
            }
        }
    }

    grid_barrier(nb);

    // ========== ALL BLOCKS: gather, 2 warps per node (64-dim halves) =============
    {
        const int lane = tid & 31;
        const int wpb = NT / 32;
        const int wid = bid * wpb + (tid >> 5);
        const int wstride = nb * wpb;        // even -> half-index fixed per warp
        const float2* ys2 = (const float2*)g_y_src;
        const float2* yd2 = (const float2*)g_y_dst;

        const int half = wid & 1;
        const int off = half * 32 + lane;    // float2 slot within row (64 per row)
        const int d = off * 2;
        const float2 bias2 = make_float2(
            ALPHA * __ldg(b_src + d)     + (1.0f - ALPHA) * __ldg(b_dst + d),
            ALPHA * __ldg(b_src + d + 1) + (1.0f - ALPHA) * __ldg(b_dst + d + 1));

        for (int h = wid; h < 2 * N; h += wstride) {
            const int i = h >> 1;
            float2 accF = make_float2(0.f, 0.f);
            float2 accB = make_float2(0.f, 0.f);

            // forward: edges with row == i (8-wide unroll)
            {
                int s = g_rs[i], n = g_outdeg[i];
                int k = 0;
                for (; k + 7 < n; k += 8) {
                    int c0 = g_fwd[s + k],     c1 = g_fwd[s + k + 1];
                    int c2 = g_fwd[s + k + 2], c3 = g_fwd[s + k + 3];
                    int c4 = g_fwd[s + k + 4], c5 = g_fwd[s + k + 5];
                    int c6 = g_fwd[s + k + 6], c7 = g_fwd[s + k + 7];
                    float w0 = g_din[c0], w1 = g_din[c1], w2 = g_din[c2], w3 = g_din[c3];
                    float w4 = g_din[c4], w5 = g_din[c5], w6 = g_din[c6], w7 = g_din[c7];
                    float2 v0 = ys2[c0 * 64 + off], v1 = ys2[c1 * 64 + off];
                    float2 v2 = ys2[c2 * 64 + off], v3 = ys2[c3 * 64 + off];
                    float2 v4 = ys2[c4 * 64 + off], v5 = ys2[c5 * 64 + off];
                    float2 v6 = ys2[c6 * 64 + off], v7 = ys2[c7 * 64 + off];
                    accF.x += w0 * v0.x + w1 * v1.x + w2 * v2.x + w3 * v3.x
                            + w4 * v4.x + w5 * v5.x + w6 * v6.x + w7 * v7.x;
                    accF.y += w0 * v0.y + w1 * v1.y + w2 * v2.y + w3 * v3.y
                            + w4 * v4.y + w5 * v5.y + w6 * v6.y + w7 * v7.y;
                }
                for (; k < n; k++) {
                    int c0 = g_fwd[s + k];
                    float w0 = g_din[c0];
                    float2 v0 = ys2[c0 * 64 + off];
                    accF.x += w0 * v0.x;
                    accF.y += w0 * v0.y;
                }
            }
            // backward: edges with col == i (8-wide unroll)
            {
                int s = g_cs[i], n = g_indeg[i];
                int k = 0;
                for (; k + 7 < n; k += 8) {
                    int r0 = g_bwd[s + k],     r1 = g_bwd[s + k + 1];
                    int r2 = g_bwd[s + k + 2], r3 = g_bwd[s + k + 3];
                    int r4 = g_bwd[s + k + 4], r5 = g_bwd[s + k + 5];
                    int r6 = g_bwd[s + k + 6], r7 = g_bwd[s + k + 7];
                    float w0 = g_dout[r0], w1 = g_dout[r1], w2 = g_dout[r2], w3 = g_dout[r3];
                    float w4 = g_dout[r4], w5 = g_dout[r5], w6 = g_dout[r6], w7 = g_dout[r7];
                    float2 v0 = yd2[r0 * 64 + off], v1 = yd2[r1 * 64 + off];
                    float2 v2 = yd2[r2 * 64 + off], v3 = yd2[r3 * 64 + off];
                    float2 v4 = yd2[r4 * 64 + off], v5 = yd2[r5 * 64 + off];
                    float2 v6 = yd2[r6 * 64 + off], v7 = yd2[r7 * 64 + off];
                    accB.x += w0 * v0.x + w1 * v1.x + w2 * v2.x + w3 * v3.x
                            + w4 * v4.x + w5 * v5.x + w6 * v6.x + w7 * v7.x;
                    accB.y += w0 * v0.y + w1 * v1.y + w2 * v2.y + w3 * v3.y
                            + w4 * v4.y + w5 * v5.y + w6 * v6.y + w7 * v7.y;
                }
                for (; k < n; k++) {
                    int r0 = g_bwd[s + k];
                    float w0 = g_dout[r0];
                    float2 v0 = yd2[r0 * 64 + off];
                    accB.x += w0 * v0.x;
                    accB.y += w0 * v0.y;
                }
            }

            float di = g_dout[i];
            float dj = g_din[i];
            float2 o = make_float2(bias2.x + di * accF.x + dj * accB.x,
                                   bias2.y + di * accF.y + dj * accB.y);
            ((float2*)out)[(size_t)i * 64 + off] = o;
        }
    }
}

// ---------------- launch --------------------------------------------------------
extern "C" void kernel_launch(void* const* d_in, const int* in_sizes, int n_in,
                              void* d_out, int out_size) {
    // Size-based input identification (order-proof).
    int idx_x = -1, idx_e = -1;
    int idxW[2] = {-1, -1}, idxB[2] = {-1, -1};
    int nw = 0, nb_ = 0;
    for (int i = 0; i < n_in; i++) {
        int s = in_sizes[i];
        if (s == out_size && idx_x < 0) idx_x = i;
        else if (s == D * D && nw < 2)  idxW[nw++] = i;
        else if (s == D && nb_ < 2)     idxB[nb_++] = i;
        else if (idx_e < 0)             idx_e = i;
    }
    bool src_first = (idx_x < idx_e);

    const float* x      = (const float*)d_in[idx_x];
    const int*   ei_raw = (const int*)d_in[idx_e];
    const float* W_src  = (const float*)d_in[src_first ? idxW[0] : idxW[1]];
    const float* W_dst  = (const float*)d_in[src_first ? idxW[1] : idxW[0]];
    const float* b_src  = (const float*)d_in[src_first ? idxB[0] : idxB[1]];
    const float* b_dst  = (const float*)d_in[src_first ? idxB[1] : idxB[0]];
    float* out = (float*)d_out;

    int N = out_size / D;            // 50000
    int E = in_sizes[idx_e] / 2;     // 800000
    if (E > MAX_EDGES) E = MAX_EDGES;

    // ONE launch: graph blocks build CSR concurrently with tf32 GEMM blocks.
    fused_kernel<<<NB, NT>>>(x, ei_raw, W_src, b_src, W_dst, b_dst, out, N, E);
}

// round 15
// speedup vs baseline: 1.3284x; 1.3284x over previous
#include <cuda_runtime.h>
#include <cuda_bf16.h>
#include <cstdint>

#define D 128
#define ALPHA 0.5f
#define MAX_NODES 50000
#define MAX_EDGES 800000
#define NB 296            // persistent grid: 2 CTAs/SM on 148 SMs, all co-resident
#define NT 256
#define GB 96             // graph blocks (block < GB); rest do GEMM

// ---------------- scratch (static device globals; no allocation) ----------------
__device__ float g_y_src[(size_t)MAX_NODES * D];   // alpha * (x @ W_src)
__device__ float g_y_dst[(size_t)MAX_NODES * D];   // (1-alpha) * (x @ W_dst)
__device__ int   g_outdeg[MAX_NODES];
__device__ int   g_indeg[MAX_NODES];
__device__ float g_dout[MAX_NODES];
__device__ float g_din[MAX_NODES];
__device__ int   g_ei[2 * MAX_EDGES];
__device__ int   g_rs[MAX_NODES];      // forward bucket start (by row)
__device__ int   g_cs[MAX_NODES];      // backward bucket start (by col)
__device__ int   g_rcur[MAX_NODES];
__device__ int   g_ccur[MAX_NODES];
__device__ int   g_fwd[MAX_EDGES];     // col indices, bucketed by row
__device__ int   g_bwd[MAX_EDGES];     // row indices, bucketed by col
__device__ unsigned g_base_f = 0, g_base_b = 0;

// global barrier (all NB blocks) + sub-barrier (GB graph blocks); generation-based
__device__ unsigned g_cnt = 0;
__device__ volatile unsigned g_gen = 0;
__device__ unsigned g_cnt2 = 0;
__device__ volatile unsigned g_gen2 = 0;

__device__ __forceinline__ void barrier_impl(unsigned* cnt, volatile unsigned* gen,
                                             int nblocks) {
    __syncthreads();
    if (threadIdx.x == 0) {
        unsigned my = *gen;
        __threadfence();
        if (atomicAdd(cnt, 1u) == (unsigned)(nblocks - 1)) {
            *cnt = 0;
            __threadfence();
            *gen = my + 1;
        } else {
            while (*gen == my) { }
        }
        __threadfence();
    }
    __syncthreads();
}
__device__ __forceinline__ void grid_barrier(int nb) { barrier_impl(&g_cnt, &g_gen, nb); }
__device__ __forceinline__ void sub_barrier()        { barrier_impl(&g_cnt2, &g_gen2, GB); }

// Dtype-agnostic index decode (exact for int32 and float32 encodings).
__device__ __forceinline__ int decode_idx(int v, int n) {
    if ((unsigned)v < (unsigned)n) return v;
    float f = __int_as_float(v);
    int r = (f > 0.0f) ? (int)f : 0;
    return ((unsigned)r < (unsigned)n) ? r : 0;
}

__device__ __forceinline__ uint32_t f2tf32(float f) {
    uint32_t u;
    asm("cvt.rna.tf32.f32 %0, %1;" : "=r"(u) : "f"(f));
    return u;
}

__device__ __forceinline__ void mma_tf32(float4& d,
                                         uint32_t a0, uint32_t a1, uint32_t a2, uint32_t a3,
                                         uint32_t b0, uint32_t b1) {
    asm volatile(
        "mma.sync.aligned.m16n8k8.row.col.f32.tf32.tf32.f32 "
        "{%0,%1,%2,%3}, {%4,%5,%6,%7}, {%8,%9}, {%0,%1,%2,%3};"
        : "+f"(d.x), "+f"(d.y), "+f"(d.z), "+f"(d.w)
        : "r"(a0), "r"(a1), "r"(a2), "r"(a3), "r"(b0), "r"(b1));
}

// GEMM tile: 64 rows x 128 cols, k-chunk 32, tf32 mma m16n8k8.
// Conflict-free strides: WSP%32==8 -> bank = 8*tig+gid; XSP%32==4 -> 4*gid+tig.
#define GEMM_TR 64
#define GEMM_KT 32
#define XSP 36
#define WSP 136

__global__ void __launch_bounds__(NT, 2)
fused_kernel(const float* __restrict__ x,
             const int* __restrict__ ei_raw,
             const float* __restrict__ W_src, const float* __restrict__ b_src,
             const float* __restrict__ W_dst, const float* __restrict__ b_dst,
             float* __restrict__ out,
             int N, int E) {
    __shared__ uint32_t Ws[GEMM_KT * WSP];   // 17.4 KB (tf32 bits)
    __shared__ uint32_t Xs[GEMM_TR * XSP];   // 9.2 KB  (tf32 bits)

    const int tid = threadIdx.x;
    const int nb = gridDim.x;
    const int bid = blockIdx.x;

    if (bid < GB) {
        // ================= GRAPH BLOCKS: decode -> degrees -> CSR =================
        const int gtid = bid * NT + tid;
        const int gstride = GB * NT;

        for (int i = gtid; i < N; i += gstride) {
            g_outdeg[i] = 0;
            g_indeg[i] = 0;
        }
        if (gtid == 0) { g_base_f = 0; g_base_b = 0; }
        sub_barrier();

        for (int i = gtid; i < 2 * E; i += gstride) {
            int v = decode_idx(ei_raw[i], N);
            g_ei[i] = v;
            if (i < E) atomicAdd(&g_outdeg[v], 1);
            else       atomicAdd(&g_indeg[v], 1);
        }
        sub_barrier();

        for (int i = gtid; i < N; i += gstride) {
            int od = g_outdeg[i];
            int id = g_indeg[i];
            g_dout[i] = (od > 0) ? rsqrtf((float)od) : 0.0f;
            g_din[i]  = (id > 0) ? rsqrtf((float)id) : 0.0f;
            int rs = (int)atomicAdd(&g_base_f, (unsigned)od);
            int cs = (int)atomicAdd(&g_base_b, (unsigned)id);
            g_rs[i] = rs;  g_rcur[i] = rs;
            g_cs[i] = cs;  g_ccur[i] = cs;
        }
        sub_barrier();

        for (int e = gtid; e < E; e += gstride) {
            int row = g_ei[e];
            int col = g_ei[E + e];
            g_fwd[atomicAdd(&g_rcur[row], 1)] = col;
            g_bwd[atomicAdd(&g_ccur[col], 1)] = row;
        }
    } else {
        // ================= GEMM BLOCKS: tf32 tensor-core GEMMs ====================
        const int tiles = (N + GEMM_TR - 1) / GEMM_TR;
        const int lane = tid & 31;
        const int warp = tid >> 5;
        const int gid = lane >> 2;       // 0..7
        const int tig = lane & 3;        // 0..3
        const int m0 = (warp & 3) * 16;  // warp's m offset in tile
        const int n0 = (warp >> 2) * 64; // warp's n offset

        for (int job = bid - GB; job < 2 * tiles; job += nb - GB) {
            const bool is_src = (job < tiles);
            const float* W = is_src ? W_src : W_dst;
            float* Y       = is_src ? g_y_src : g_y_dst;
            const float scale = is_src ? ALPHA : (1.0f - ALPHA);
            const int row0 = (is_src ? job : job - tiles) * GEMM_TR;

            float4 acc[8];
#pragma unroll
            for (int t = 0; t < 8; t++) acc[t] = make_float4(0.f, 0.f, 0.f, 0.f);

            for (int kt = 0; kt < D; kt += GEMM_KT) {
#pragma unroll
                for (int i = tid; i < GEMM_KT * (D / 4); i += NT) {
                    int kk = i >> 5, d4 = i & 31;
                    float4 v = ((const float4*)(W + (kt + kk) * D))[d4];
                    uint4 u = make_uint4(f2tf32(v.x), f2tf32(v.y),
                                         f2tf32(v.z), f2tf32(v.w));
                    *(uint4*)&Ws[kk * WSP + d4 * 4] = u;
                }
#pragma unroll
                for (int i = tid; i < GEMM_TR * (GEMM_KT / 4); i += NT) {
                    int r = i >> 3, c4 = i & 7;
                    int gr = row0 + r;
                    float4 v = (gr < N)
                        ? ((const float4*)(x + (size_t)gr * D + kt))[c4]
                        : make_float4(0.f, 0.f, 0.f, 0.f);
                    uint4 u = make_uint4(f2tf32(v.x), f2tf32(v.y),
                                         f2tf32(v.z), f2tf32(v.w));
                    *(uint4*)&Xs[r * XSP + c4 * 4] = u;
                }
                __syncthreads();

#pragma unroll
                for (int ks = 0; ks < GEMM_KT; ks += 8) {
                    uint32_t a0 = Xs[(m0 + gid)     * XSP + ks + tig];
                    uint32_t a1 = Xs[(m0 + gid + 8) * XSP + ks + tig];
                    uint32_t a2 = Xs[(m0 + gid)     * XSP + ks + tig + 4];
                    uint32_t a3 = Xs[(m0 + gid + 8) * XSP + ks + tig + 4];
#pragma unroll
                    for (int t = 0; t < 8; t++) {
                        uint32_t b0 = Ws[(ks + tig)     * WSP + n0 + t * 8 + gid];
                        uint32_t b1 = Ws[(ks + tig + 4) * WSP + n0 + t * 8 + gid];
                        mma_tf32(acc[t], a0, a1, a2, a3, b0, b1);
                    }
                }
                __syncthreads();
            }

            int r0 = row0 + m0 + gid;
            int r1 = r0 + 8;
#pragma unroll
            for (int t = 0; t < 8; t++) {
                int col = n0 + t * 8 + 2 * tig;
                if (r0 < N) {
                    float2 v = make_float2(scale * acc[t].x, scale * acc[t].y);
                    *(float2*)&Y[(size_t)r0 * D + col] = v;
                }
                if (r1 < N) {
                    float2 v = make_float2(scale * acc[t].z, scale * acc[t].w);
                    *(float2*)&Y[(size_t)r1 * D + col] = v;
                }
            }
        }
    }

    grid_barrier(nb);

    // ===== ALL BLOCKS: gather, one warp per node, float4, 8-wide unroll ==========
    {
        const int lane = tid & 31;
        const int wpb = NT / 32;
        const int wid = bid * wpb + (tid >> 5);
        const int wstride = nb * wpb;
        const float4* ys = (const float4*)g_y_src;
        const float4* yd = (const float4*)g_y_dst;

        int d = lane * 4;
        float4 bias4 = make_float4(
            ALPHA * __ldg(b_src + d + 0) + (1.0f - ALPHA) * __ldg(b_dst + d + 0),
            ALPHA * __ldg(b_src + d + 1) + (1.0f - ALPHA) * __ldg(b_dst + d + 1),
            ALPHA * __ldg(b_src + d + 2) + (1.0f - ALPHA) * __ldg(b_dst + d + 2),
            ALPHA * __ldg(b_src + d + 3) + (1.0f - ALPHA) * __ldg(b_dst + d + 3));

        for (int i = wid; i < N; i += wstride) {
            float4 accF = make_float4(0.f, 0.f, 0.f, 0.f);
            float4 accB = make_float4(0.f, 0.f, 0.f, 0.f);

            // forward: edges with row == i (8-wide unroll, batched loads)
            {
                int s = g_rs[i], n = g_outdeg[i];
                int k = 0;
                for (; k + 7 < n; k += 8) {
                    int c0 = g_fwd[s + k],     c1 = g_fwd[s + k + 1];
                    int c2 = g_fwd[s + k + 2], c3 = g_fwd[s + k + 3];
                    int c4 = g_fwd[s + k + 4], c5 = g_fwd[s + k + 5];
                    int c6 = g_fwd[s + k + 6], c7 = g_fwd[s + k + 7];
                    float w0 = g_din[c0], w1 = g_din[c1], w2 = g_din[c2], w3 = g_din[c3];
                    float w4 = g_din[c4], w5 = g_din[c5], w6 = g_din[c6], w7 = g_din[c7];
                    float4 v0 = ys[c0 * 32 + lane], v1 = ys[c1 * 32 + lane];
                    float4 v2 = ys[c2 * 32 + lane], v3 = ys[c3 * 32 + lane];
                    float4 v4 = ys[c4 * 32 + lane], v5 = ys[c5 * 32 + lane];
                    float4 v6 = ys[c6 * 32 + lane], v7 = ys[c7 * 32 + lane];
                    accF.x += w0 * v0.x + w1 * v1.x + w2 * v2.x + w3 * v3.x
                            + w4 * v4.x + w5 * v5.x + w6 * v6.x + w7 * v7.x;
                    accF.y += w0 * v0.y + w1 * v1.y + w2 * v2.y + w3 * v3.y
                            + w4 * v4.y + w5 * v5.y + w6 * v6.y + w7 * v7.y;
                    accF.z += w0 * v0.z + w1 * v1.z + w2 * v2.z + w3 * v3.z
                            + w4 * v4.z + w5 * v5.z + w6 * v6.z + w7 * v7.z;
                    accF.w += w0 * v0.w + w1 * v1.w + w2 * v2.w + w3 * v3.w
                            + w4 * v4.w + w5 * v5.w + w6 * v6.w + w7 * v7.w;
                }
                for (; k < n; k++) {
                    int c0 = g_fwd[s + k];
                    float w0 = g_din[c0];
                    float4 v0 = ys[c0 * 32 + lane];
                    accF.x += w0 * v0.x; accF.y += w0 * v0.y;
                    accF.z += w0 * v0.z; accF.w += w0 * v0.w;
                }
            }
            // backward: edges with col == i (8-wide unroll)
            {
                int s = g_cs[i], n = g_indeg[i];
                int k = 0;
                for (; k + 7 < n; k += 8) {
                    int r0 = g_bwd[s + k],     r1 = g_bwd[s + k + 1];
                    int r2 = g_bwd[s + k + 2], r3 = g_bwd[s + k + 3];
                    int r4 = g_bwd[s + k + 4], r5 = g_bwd[s + k + 5];
                    int r6 = g_bwd[s + k + 6], r7 = g_bwd[s + k + 7];
                    float w0 = g_dout[r0], w1 = g_dout[r1], w2 = g_dout[r2], w3 = g_dout[r3];
                    float w4 = g_dout[r4], w5 = g_dout[r5], w6 = g_dout[r6], w7 = g_dout[r7];
                    float4 v0 = yd[r0 * 32 + lane], v1 = yd[r1 * 32 + lane];
                    float4 v2 = yd[r2 * 32 + lane], v3 = yd[r3 * 32 + lane];
                    float4 v4 = yd[r4 * 32 + lane], v5 = yd[r5 * 32 + lane];
                    float4 v6 = yd[r6 * 32 + lane], v7 = yd[r7 * 32 + lane];
                    accB.x += w0 * v0.x + w1 * v1.x + w2 * v2.x + w3 * v3.x
                            + w4 * v4.x + w5 * v5.x + w6 * v6.x + w7 * v7.x;
                    accB.y += w0 * v0.y + w1 * v1.y + w2 * v2.y + w3 * v3.y
                            + w4 * v4.y + w5 * v5.y + w6 * v6.y + w7 * v7.y;
                    accB.z += w0 * v0.z + w1 * v1.z + w2 * v2.z + w3 * v3.z
                            + w4 * v4.z + w5 * v5.z + w6 * v6.z + w7 * v7.z;
                    accB.w += w0 * v0.w + w1 * v1.w + w2 * v2.w + w3 * v3.w
                            + w4 * v4.w + w5 * v5.w + w6 * v6.w + w7 * v7.w;
                }
                for (; k < n; k++) {
                    int r0 = g_bwd[s + k];
                    float w0 = g_dout[r0];
                    float4 v0 = yd[r0 * 32 + lane];
                    accB.x += w0 * v0.x; accB.y += w0 * v0.y;
                    accB.z += w0 * v0.z; accB.w += w0 * v0.w;
                }
            }

            float di = g_dout[i];
            float dj = g_din[i];
            float4 o = make_float4(
                bias4.x + di * accF.x + dj * accB.x,
                bias4.y + di * accF.y + dj * accB.y,
                bias4.z + di * accF.z + dj * accB.z,
                bias4.w + di * accF.w + dj * accB.w);
            ((float4*)out)[i * 32 + lane] = o;
        }
    }
}

// ---------------- launch --------------------------------------------------------
extern "C" void kernel_launch(void* const* d_in, const int* in_sizes, int n_in,
                              void* d_out, int out_size) {
    // Size-based input identification (order-proof).
    int idx_x = -1, idx_e = -1;
    int idxW[2] = {-1, -1}, idxB[2] = {-1, -1};
    int nw = 0, nb_ = 0;
    for (int i = 0; i < n_in; i++) {
        int s = in_sizes[i];
        if (s == out_size && idx_x < 0) idx_x = i;
        else if (s == D * D && nw < 2)  idxW[nw++] = i;
        else if (s == D && nb_ < 2)     idxB[nb_++] = i;
        else if (idx_e < 0)             idx_e = i;
    }
    bool src_first = (idx_x < idx_e);

    const float* x      = (const float*)d_in[idx_x];
    const int*   ei_raw = (const int*)d_in[idx_e];
    const float* W_src  = (const float*)d_in[src_first ? idxW[0] : idxW[1]];
    const float* W_dst  = (const float*)d_in[src_first ? idxW[1] : idxW[0]];
    const float* b_src  = (const float*)d_in[src_first ? idxB[0] : idxB[1]];
    const float* b_dst  = (const float*)d_in[src_first ? idxB[1] : idxB[0]];
    float* out = (float*)d_out;

    int N = out_size / D;            // 50000
    int E = in_sizes[idx_e] / 2;     // 800000
    if (E > MAX_EDGES) E = MAX_EDGES;

    // ONE launch: graph blocks build CSR concurrently with tf32 GEMM blocks.
    fused_kernel<<<NB, NT>>>(x, ei_raw, W_src, b_src, W_dst, b_dst, out, N, E);
}